// round 6
// baseline (speedup 1.0000x reference)
#include <cuda_runtime.h>

// MakeCutouts: 64 cutouts of [4,3,512,512] fp32 -> bilinear 224x224, out [256,3,224,224].
//
// Vertical row-reuse formulation: out(i,j) = h(iy0)*(1-fy) + h(iy1)*fy where
// h(r) = x[r,ix0]*(1-fx) + x[r,ix1]*fx is a horizontally-blended source row.
// A thread owns one output column j and walks CHUNK=16 consecutive output rows,
// caching h0/h1 per plane in registers. When the source window advances by one
// row (scale<2, ~40% of steps at E[scale]=1.64) only ONE new row is gathered
// (2 LDG/plane instead of 4), cutting L1 wavefronts ~18%. Row-advance logic is
// warp-uniform (depends only on n,i). Warp spans 32 consecutive j -> coalesced
// streaming stores. Planes split 6+6 across blockIdx.z to keep blends in regs.

#define IMG   512
#define S     224
#define CUTN  64
#define NCH   12
#define PH    6              // planes per block
#define CHUNK 16
#define PLANE (IMG*IMG)
#define OPLANE (S*S)

__global__ __launch_bounds__(S, 4)
void make_cutouts_kernel(const float* __restrict__ x,
                         const int*   __restrict__ sizes,
                         const int*   __restrict__ offsetx,
                         const int*   __restrict__ offsety,
                         float*       __restrict__ out)
{
    const int j     = threadIdx.x;              // output column
    const int n     = blockIdx.y;               // cutout
    const int pbase = blockIdx.z * PH;          // first plane of this half
    const int i0    = blockIdx.x * CHUNK;       // first output row of chunk

    const int   size  = __ldg(sizes + n);
    const float scale = (float)size * (1.0f / (float)S);
    const int   ox    = __ldg(offsetx + n);
    const int   oy    = __ldg(offsety + n);
    const int   sm1   = size - 1;

    // x taps — fixed for the whole column walk
    float srcx = fmaxf(scale * ((float)j + 0.5f) - 0.5f, 0.0f);
    int   ix0  = (int)floorf(srcx);
    const float fx = srcx - (float)ix0;
    ix0 = min(ix0, sm1);
    const int ix1 = min(ix0 + 1, sm1);
    const float wx1 = fx, wx0 = 1.0f - fx;
    const int c0 = ox + ix0;
    const int c1 = ox + ix1;

    const float* __restrict__ xp = x + pbase * PLANE;

    float h0[PH], h1[PH];
    int piy0 = -1000000, piy1 = -1000000;

    int obase = ((n * NCH + pbase) * S + i0) * S + j;

    #pragma unroll 1
    for (int ii = 0; ii < CHUNK; ++ii) {
        const int i = i0 + ii;
        float srcy = fmaxf(scale * ((float)i + 0.5f) - 0.5f, 0.0f);
        int   iy0  = (int)floorf(srcy);
        const float fy = srcy - (float)iy0;      // frac before clamp (matches ref)
        iy0 = min(iy0, sm1);
        const int iy1 = min(iy0 + 1, sm1);

        // --- update h0 (row iy0) --- (all branches warp-uniform)
        if (iy0 == piy1) {
            #pragma unroll
            for (int p = 0; p < PH; ++p) h0[p] = h1[p];
        } else if (iy0 != piy0) {
            const float* __restrict__ r = xp + (oy + iy0) * IMG;
            #pragma unroll
            for (int p = 0; p < PH; ++p)
                h0[p] = fmaf(__ldg(r + p * PLANE + c1), wx1,
                             __ldg(r + p * PLANE + c0) * wx0);
        }
        // --- update h1 (row iy1) ---
        if (iy1 == iy0) {
            #pragma unroll
            for (int p = 0; p < PH; ++p) h1[p] = h0[p];
        } else if (iy1 != piy1) {
            const float* __restrict__ r = xp + (oy + iy1) * IMG;
            #pragma unroll
            for (int p = 0; p < PH; ++p)
                h1[p] = fmaf(__ldg(r + p * PLANE + c1), wx1,
                             __ldg(r + p * PLANE + c0) * wx0);
        }

        const float wy1 = fy, wy0 = 1.0f - fy;
        #pragma unroll
        for (int p = 0; p < PH; ++p)
            __stcs(out + obase + p * OPLANE, fmaf(h1[p], wy1, h0[p] * wy0));
        obase += S;

        piy0 = iy0;
        piy1 = iy1;
    }
}

extern "C" void kernel_launch(void* const* d_in, const int* in_sizes, int n_in,
                              void* d_out, int out_size)
{
    const float* x       = (const float*)d_in[0];
    const int*   sizes   = (const int*)d_in[1];
    const int*   offsetx = (const int*)d_in[2];
    const int*   offsety = (const int*)d_in[3];
    float* out = (float*)d_out;

    dim3 grid(S / CHUNK, CUTN, NCH / PH);   // 14 x 64 x 2
    dim3 block(S);                          // 224 threads = 7 warps, warp = 32 consecutive j
    make_cutouts_kernel<<<grid, block>>>(x, sizes, offsetx, offsety, out);
}